// round 7
// baseline (speedup 1.0000x reference)
#include <cuda_runtime.h>

#define TOKENS 8192
#define IN_F   4096
#define OUT_F  4096
#define RNK    16

#define NS_A 3.4445f
#define NS_Bc (-4.775f)
#define NS_Cc 2.0315f
#define NS_EPS 1e-7f

// ---------------- device scratch (no allocations allowed) ----------------
__device__ float g_KA[RNK * RNK];   // A @ A^T   (16x16)
__device__ float g_KB[RNK * RNK];   // B^T @ B   (16x16)
__device__ float g_Cs[RNK * RNK];   // alpha * C5 (16x16)
__device__ float g_xA[TOKENS * RNK];  // x @ A^T   [8192,16]
__device__ float g_Bc[OUT_F * RNK];   // B @ Cs    [4096,16]

// ---------------- packed f32x2 helpers (sm_103a FFMA2 path) ----------------
__device__ __forceinline__ unsigned long long pack2(float lo, float hi) {
    unsigned long long r;
    asm("mov.b64 %0, {%1, %2};" : "=l"(r) : "f"(lo), "f"(hi));
    return r;
}
__device__ __forceinline__ void unpack2(unsigned long long v, float& lo, float& hi) {
    asm("mov.b64 {%0, %1}, %2;" : "=f"(lo), "=f"(hi) : "l"(v));
}
__device__ __forceinline__ unsigned long long ffma2(unsigned long long a,
                                                    unsigned long long b,
                                                    unsigned long long c) {
    unsigned long long d;
    asm("fma.rn.f32x2 %0, %1, %2, %3;" : "=l"(d) : "l"(a), "l"(b), "l"(c));
    return d;
}

// =====================================================================
// K1: gram matrices. block 0: K_A = A A^T ; block 1: K_B = B^T B
// =====================================================================
__global__ void k_gram(const float* __restrict__ A, const float* __restrict__ B) {
    __shared__ float s[16 * 513];   // 32.8 KB
    int t = threadIdx.x;
    int r1 = t >> 4, r2 = t & 15;
    float sum = 0.f;

    if (blockIdx.x == 0) {
        // K_A[r1][r2] = sum_k A[r1,k] A[r2,k]; A row-major [16, 4096]
        const float4* A4 = reinterpret_cast<const float4*>(A);
        for (int c = 0; c < IN_F; c += 512) {
            for (int idx = t; idx < 16 * 128; idx += 256) {
                int r = idx >> 7;         // 0..15
                int k4 = idx & 127;       // 0..127
                float4 v = A4[r * (IN_F / 4) + (c >> 2) + k4];
                s[r * 513 + k4 * 4 + 0] = v.x;
                s[r * 513 + k4 * 4 + 1] = v.y;
                s[r * 513 + k4 * 4 + 2] = v.z;
                s[r * 513 + k4 * 4 + 3] = v.w;
            }
            __syncthreads();
            for (int k = 0; k < 512; ++k)
                sum += s[r1 * 513 + k] * s[r2 * 513 + k];
            __syncthreads();
        }
        g_KA[t] = sum;
    } else {
        // K_B[r1][r2] = sum_j B[j,r1] B[j,r2]; B row-major [4096, 16]
        const float4* B4 = reinterpret_cast<const float4*>(B);
        for (int c = 0; c < OUT_F; c += 512) {
            for (int idx = t; idx < 512 * 4; idx += 256) {   // 2048 float4
                float4 v = B4[c * 4 + idx];
                s[idx * 4 + 0] = v.x;
                s[idx * 4 + 1] = v.y;
                s[idx * 4 + 2] = v.z;
                s[idx * 4 + 3] = v.w;
            }
            __syncthreads();
            for (int j = 0; j < 512; ++j)
                sum += s[j * 16 + r1] * s[j * 16 + r2];
            __syncthreads();
        }
        g_KB[t] = sum;
    }
}

// =====================================================================
// K2: Newton-Schulz on the 16x16 core.  C0 = I/(alpha+eps);
//   D = C^T K_B C; E = K_A D; C <- aC + b C E + c C E E
//   g_Cs = alpha * C5
// =====================================================================
__global__ void k_ns() {
    __shared__ float KA[256], KB[256], C[256], T[256], D[256], E[256], F[256], G2[256];
    __shared__ float s_alpha;
    int t = threadIdx.x;
    int i = t >> 4, j = t & 15;
    KA[t] = g_KA[t];
    KB[t] = g_KB[t];
    __syncthreads();
    if (t == 0) {
        float n2 = 0.f;
        for (int p = 0; p < 16; ++p)
            for (int q = 0; q < 16; ++q)
                n2 += KB[p * 16 + q] * KA[q * 16 + p];   // tr(K_B K_A)
        s_alpha = sqrtf(n2);
    }
    __syncthreads();
    float alpha = s_alpha;
    float sc = 1.f / (alpha + NS_EPS);
    C[t] = (i == j) ? sc : 0.f;
    __syncthreads();

    for (int it = 0; it < 5; ++it) {
        float acc = 0.f;
        #pragma unroll
        for (int k = 0; k < 16; ++k) acc += KB[i * 16 + k] * C[k * 16 + j];
        T[t] = acc; __syncthreads();                 // T = K_B C

        acc = 0.f;
        #pragma unroll
        for (int k = 0; k < 16; ++k) acc += C[k * 16 + i] * T[k * 16 + j];
        D[t] = acc; __syncthreads();                 // D = C^T T

        acc = 0.f;
        #pragma unroll
        for (int k = 0; k < 16; ++k) acc += KA[i * 16 + k] * D[k * 16 + j];
        E[t] = acc; __syncthreads();                 // E = K_A D

        acc = 0.f;
        #pragma unroll
        for (int k = 0; k < 16; ++k) acc += C[i * 16 + k] * E[k * 16 + j];
        F[t] = acc; __syncthreads();                 // F = C E

        acc = 0.f;
        #pragma unroll
        for (int k = 0; k < 16; ++k) acc += F[i * 16 + k] * E[k * 16 + j];
        G2[t] = acc; __syncthreads();                // G2 = F E

        float cn = NS_A * C[t] + NS_Bc * F[t] + NS_Cc * G2[t];
        C[t] = cn;           // each thread touches only its own element
        __syncthreads();
    }
    g_Cs[t] = alpha * C[t];
}

// =====================================================================
// K3: xA = x @ A^T  [8192,16].  4 rows per warp, A reused across 4 rows.
// =====================================================================
__global__ void k_xa(const float* __restrict__ x, const float* __restrict__ A) {
    int w = threadIdx.x >> 5, l = threadIdx.x & 31;
    int i0 = (blockIdx.x * 8 + w) * 4;
    const float4* x4 = reinterpret_cast<const float4*>(x);
    const float4* A4 = reinterpret_cast<const float4*>(A);
    const int KQ = IN_F / 4;   // 1024 float4 per row

    float acc[4][16];
    #pragma unroll
    for (int rr = 0; rr < 4; ++rr)
        #pragma unroll
        for (int r = 0; r < 16; ++r) acc[rr][r] = 0.f;

    for (int tt = 0; tt < 32; ++tt) {
        int k4 = l + (tt << 5);
        float4 xv0 = x4[(i0 + 0) * KQ + k4];
        float4 xv1 = x4[(i0 + 1) * KQ + k4];
        float4 xv2 = x4[(i0 + 2) * KQ + k4];
        float4 xv3 = x4[(i0 + 3) * KQ + k4];
        #pragma unroll
        for (int r = 0; r < 16; ++r) {
            float4 av = A4[r * KQ + k4];
            acc[0][r] += xv0.x * av.x + xv0.y * av.y + xv0.z * av.z + xv0.w * av.w;
            acc[1][r] += xv1.x * av.x + xv1.y * av.y + xv1.z * av.z + xv1.w * av.w;
            acc[2][r] += xv2.x * av.x + xv2.y * av.y + xv2.z * av.z + xv2.w * av.w;
            acc[3][r] += xv3.x * av.x + xv3.y * av.y + xv3.z * av.z + xv3.w * av.w;
        }
    }
    // warp butterfly reduce; then lane r writes column r
    #pragma unroll
    for (int rr = 0; rr < 4; ++rr)
        #pragma unroll
        for (int r = 0; r < 16; ++r)
            #pragma unroll
            for (int off = 16; off; off >>= 1)
                acc[rr][r] += __shfl_xor_sync(0xffffffffu, acc[rr][r], off);
    #pragma unroll
    for (int rr = 0; rr < 4; ++rr)
        #pragma unroll
        for (int r = 0; r < 16; ++r)
            if (l == r) g_xA[(i0 + rr) * 16 + r] = acc[rr][r];
}

// =====================================================================
// K4: Bc = B @ (alpha*C)   [4096,16]
// =====================================================================
__global__ void k_bc(const float* __restrict__ B) {
    __shared__ float Cs[256];
    int t = threadIdx.x;
    Cs[t] = g_Cs[t];
    __syncthreads();
    int g = blockIdx.x * 256 + t;
    int j = g >> 4, r2 = g & 15;
    float s = 0.f;
    #pragma unroll
    for (int r = 0; r < 16; ++r) s += B[j * 16 + r] * Cs[r * 16 + r2];
    g_Bc[g] = s;
}

// =====================================================================
// K5: main fused GEMM.
//   out[i,j] = sum_k x[i,k] W[j,k]  +  bias[j]  +  sum_r xA[i,r] Bc[j,r]
// 128x128x16 tiles, 256 threads, 8x8 per thread, packed f32x2 FFMA2 math.
// LoRA term runs as one extra BK=16 tile iteration with xA/Bc tiles.
// =====================================================================
#define COMPUTE16()                                                              \
    _Pragma("unroll")                                                            \
    for (int kk = 0; kk < 16; ++kk) {                                            \
        const float* xrow = &Xs[kk * 132 + (ty << 3)];                           \
        float4 xa_ = *reinterpret_cast<const float4*>(xrow);                     \
        float4 xb_ = *reinterpret_cast<const float4*>(xrow + 4);                 \
        const ulonglong2* wrow =                                                 \
            reinterpret_cast<const ulonglong2*>(&Ws[kk * 132 + (tx << 3)]);      \
        ulonglong2 wA_ = wrow[0];                                                \
        ulonglong2 wB_ = wrow[1];                                                \
        float xs_[8] = {xa_.x, xa_.y, xa_.z, xa_.w, xb_.x, xb_.y, xb_.z, xb_.w}; \
        _Pragma("unroll")                                                        \
        for (int m = 0; m < 8; ++m) {                                            \
            unsigned long long xm = pack2(xs_[m], xs_[m]);                       \
            acc2[m][0] = ffma2(xm, wA_.x, acc2[m][0]);                           \
            acc2[m][1] = ffma2(xm, wA_.y, acc2[m][1]);                           \
            acc2[m][2] = ffma2(xm, wB_.x, acc2[m][2]);                           \
            acc2[m][3] = ffma2(xm, wB_.y, acc2[m][3]);                           \
        }                                                                        \
    }

__device__ __forceinline__ void sts_t(float* S, int lk, int i, float4 v) {
    S[(lk * 4 + 0) * 132 + i] = v.x;
    S[(lk * 4 + 1) * 132 + i] = v.y;
    S[(lk * 4 + 2) * 132 + i] = v.z;
    S[(lk * 4 + 3) * 132 + i] = v.w;
}

__global__ __launch_bounds__(256, 2)
void k_main(const float* __restrict__ x, const float* __restrict__ W,
            const float* __restrict__ bias, float* __restrict__ out) {
    __shared__ __align__(16) float Xs[16 * 132];
    __shared__ __align__(16) float Ws[16 * 132];
    const int K4 = IN_F / 4;

    int t  = threadIdx.x;
    int tx = t & 15, ty = t >> 4;
    int row0 = blockIdx.y << 7;
    int col0 = blockIdx.x << 7;

    const float4* x4  = reinterpret_cast<const float4*>(x);
    const float4* w4  = reinterpret_cast<const float4*>(W);
    const float4* xa4 = reinterpret_cast<const float4*>(g_xA);
    const float4* bc4 = reinterpret_cast<const float4*>(g_Bc);

    int li0 = t >> 2;        // 0..63
    int li1 = li0 + 64;      // 64..127
    int lk  = t & 3;         // float4 slot within 16-wide K slab

    unsigned long long acc2[8][4];
    {
        unsigned long long z = pack2(0.f, 0.f);
        #pragma unroll
        for (int m = 0; m < 8; ++m) {
            acc2[m][0] = z; acc2[m][1] = z; acc2[m][2] = z; acc2[m][3] = z;
        }
    }

    float4 px0 = x4[(row0 + li0) * K4 + lk];
    float4 px1 = x4[(row0 + li1) * K4 + lk];
    float4 pw0 = w4[(col0 + li0) * K4 + lk];
    float4 pw1 = w4[(col0 + li1) * K4 + lk];

    for (int k0 = 0; k0 < IN_F; k0 += 16) {
        sts_t(Xs, lk, li0, px0);
        sts_t(Xs, lk, li1, px1);
        sts_t(Ws, lk, li0, pw0);
        sts_t(Ws, lk, li1, pw1);
        __syncthreads();

        if (k0 + 16 < IN_F) {
            int kb = (k0 + 16) >> 2;
            px0 = x4[(row0 + li0) * K4 + kb + lk];
            px1 = x4[(row0 + li1) * K4 + kb + lk];
            pw0 = w4[(col0 + li0) * K4 + kb + lk];
            pw1 = w4[(col0 + li1) * K4 + kb + lk];
        } else {
            // prefetch LoRA tiles (xA is [*,16] = 4 float4/row; Bc same)
            px0 = xa4[(row0 + li0) * 4 + lk];
            px1 = xa4[(row0 + li1) * 4 + lk];
            pw0 = bc4[(col0 + li0) * 4 + lk];
            pw1 = bc4[(col0 + li1) * 4 + lk];
        }

        COMPUTE16();
        __syncthreads();
    }

    // --- LoRA rank-16 contraction as one extra tile iteration ---
    sts_t(Xs, lk, li0, px0);
    sts_t(Xs, lk, li1, px1);
    sts_t(Ws, lk, li0, pw0);
    sts_t(Ws, lk, li1, pw1);
    __syncthreads();
    COMPUTE16();

    // --- epilogue: + bias, store ---
    float4 bA = *reinterpret_cast<const float4*>(bias + col0 + (tx << 3));
    float4 bB = *reinterpret_cast<const float4*>(bias + col0 + (tx << 3) + 4);
    #pragma unroll
    for (int m = 0; m < 8; ++m) {
        float o0, o1, o2, o3, o4v, o5, o6, o7;
        unpack2(acc2[m][0], o0, o1);
        unpack2(acc2[m][1], o2, o3);
        unpack2(acc2[m][2], o4v, o5);
        unpack2(acc2[m][3], o6, o7);
        float4 ra = make_float4(o0 + bA.x, o1 + bA.y, o2 + bA.z, o3 + bA.w);
        float4 rb = make_float4(o4v + bB.x, o5 + bB.y, o6 + bB.z, o7 + bB.w);
        size_t off = (size_t)(row0 + (ty << 3) + m) * OUT_F + col0 + (tx << 3);
        *reinterpret_cast<float4*>(out + off)     = ra;
        *reinterpret_cast<float4*>(out + off + 4) = rb;
    }
}

// =====================================================================
extern "C" void kernel_launch(void* const* d_in, const int* in_sizes, int n_in,
                              void* d_out, int out_size) {
    const float* x    = (const float*)d_in[0];   // [8192, 4096]
    const float* W    = (const float*)d_in[1];   // [4096, 4096]
    const float* bias = (const float*)d_in[2];   // [4096]
    const float* A    = (const float*)d_in[3];   // [16, 4096]
    const float* B    = (const float*)d_in[4];   // [4096, 16]
    float* out = (float*)d_out;                  // [8192, 4096]

    k_gram<<<2, 256>>>(A, B);
    k_ns<<<1, 256>>>();
    k_bc<<<256, 256>>>(B);
    k_xa<<<TOKENS / 32, 256>>>(x, A);
    dim3 grid(OUT_F / 128, TOKENS / 128);
    k_main<<<grid, 256>>>(x, W, bias, out);
}

// round 10
// speedup vs baseline: 2.0879x; 2.0879x over previous
#include <cuda_runtime.h>
#include <cuda_bf16.h>
#include <cstdint>

#define TOKENS 8192
#define IN_F   4096
#define OUT_F  4096
#define RNK    16

#define NS_A 3.4445f
#define NS_Bc (-4.775f)
#define NS_Cc 2.0315f
#define NS_EPS 1e-7f

#define NCH 385          // 3*128 split-bf16 chunks (BK=32) + 1 LoRA chunk
#define STAGES 4
#define STAGE_BYTES 16384   // A 8KB + B 8KB

// ---------------- device scratch (no allocations allowed) ----------------
__device__ __align__(16) __nv_bfloat16 g_xhi[TOKENS * IN_F];
__device__ __align__(16) __nv_bfloat16 g_xlo[TOKENS * IN_F];
__device__ __align__(16) __nv_bfloat16 g_whi[OUT_F * IN_F];
__device__ __align__(16) __nv_bfloat16 g_wlo[OUT_F * IN_F];
__device__ __align__(16) __nv_bfloat16 g_xAh[TOKENS * 32];  // bf16(x@A^T), cols 16..31 zero
__device__ __align__(16) __nv_bfloat16 g_Bch[OUT_F * 32];   // bf16(B @ alpha*C5), padded
__device__ float g_KA[RNK * RNK];
__device__ float g_KB[RNK * RNK];
__device__ float g_Cs[RNK * RNK];

// ---------------- PTX helpers (sm_80-baseline instructions only) ----------
__device__ __forceinline__ uint32_t smem_u32(const void* p) {
    uint32_t a;
    asm("{ .reg .u64 t; cvta.to.shared.u64 t, %1; cvt.u32.u64 %0, t; }" : "=r"(a) : "l"(p));
    return a;
}
__device__ __forceinline__ void cp16(uint32_t s, const void* g) {
    asm volatile("cp.async.cg.shared.global [%0], [%1], 16;" :: "r"(s), "l"(g));
}
__device__ __forceinline__ void cp_commit() {
    asm volatile("cp.async.commit_group;" ::: "memory");
}
template <int N>
__device__ __forceinline__ void cp_wait() {
    asm volatile("cp.async.wait_group %0;" :: "n"(N) : "memory");
}
__device__ __forceinline__ void ldsm4(uint32_t* d, uint32_t a) {
    asm volatile("ldmatrix.sync.aligned.m8n8.x4.shared.b16 {%0,%1,%2,%3}, [%4];"
                 : "=r"(d[0]), "=r"(d[1]), "=r"(d[2]), "=r"(d[3]) : "r"(a));
}
__device__ __forceinline__ void mma16816(float* d, const uint32_t* a, uint32_t b0, uint32_t b1) {
    asm volatile(
        "mma.sync.aligned.m16n8k16.row.col.f32.bf16.bf16.f32 "
        "{%0,%1,%2,%3}, {%4,%5,%6,%7}, {%8,%9}, {%0,%1,%2,%3};"
        : "+f"(d[0]), "+f"(d[1]), "+f"(d[2]), "+f"(d[3])
        : "r"(a[0]), "r"(a[1]), "r"(a[2]), "r"(a[3]), "r"(b0), "r"(b1));
}

// swizzled smem byte offset for row-major [128][32] bf16 tile (64B rows).
// phase(m,c) = 4*(m&1) + (c ^ (m>>1)&3): all 8 ldmatrix rows hit distinct 16B banks.
__device__ __forceinline__ uint32_t sw(uint32_t row, uint32_t cb) {
    return row * 64u + ((cb ^ ((row >> 1) & 3u)) << 4);
}

// =====================================================================
// split fp32 -> bf16 hi + bf16 residual
// =====================================================================
__device__ __forceinline__ void split1(float v, unsigned short& h, unsigned short& l) {
    __nv_bfloat16 hb = __float2bfloat16_rn(v);
    h = __bfloat16_as_ushort(hb);
    float r = v - __bfloat162float(hb);
    l = __bfloat16_as_ushort(__float2bfloat16_rn(r));
}
__global__ void k_split_x(const float4* __restrict__ src) {
    int i = blockIdx.x * 256 + threadIdx.x;
    float4 v = src[i];
    ushort4 h, l;
    split1(v.x, h.x, l.x); split1(v.y, h.y, l.y);
    split1(v.z, h.z, l.z); split1(v.w, h.w, l.w);
    reinterpret_cast<ushort4*>(g_xhi)[i] = h;
    reinterpret_cast<ushort4*>(g_xlo)[i] = l;
}
__global__ void k_split_w(const float4* __restrict__ src) {
    int i = blockIdx.x * 256 + threadIdx.x;
    float4 v = src[i];
    ushort4 h, l;
    split1(v.x, h.x, l.x); split1(v.y, h.y, l.y);
    split1(v.z, h.z, l.z); split1(v.w, h.w, l.w);
    reinterpret_cast<ushort4*>(g_whi)[i] = h;
    reinterpret_cast<ushort4*>(g_wlo)[i] = l;
}

// =====================================================================
// K1: gram matrices. block 0: K_A = A A^T ; block 1: K_B = B^T B
// =====================================================================
__global__ void k_gram(const float* __restrict__ A, const float* __restrict__ B) {
    __shared__ float s[16 * 513];
    int t = threadIdx.x;
    int r1 = t >> 4, r2 = t & 15;
    float sum = 0.f;

    if (blockIdx.x == 0) {
        const float4* A4 = reinterpret_cast<const float4*>(A);
        for (int c = 0; c < IN_F; c += 512) {
            for (int idx = t; idx < 16 * 128; idx += 256) {
                int r = idx >> 7;
                int k4 = idx & 127;
                float4 v = A4[r * (IN_F / 4) + (c >> 2) + k4];
                s[r * 513 + k4 * 4 + 0] = v.x;
                s[r * 513 + k4 * 4 + 1] = v.y;
                s[r * 513 + k4 * 4 + 2] = v.z;
                s[r * 513 + k4 * 4 + 3] = v.w;
            }
            __syncthreads();
            for (int k = 0; k < 512; ++k)
                sum += s[r1 * 513 + k] * s[r2 * 513 + k];
            __syncthreads();
        }
        g_KA[t] = sum;
    } else {
        const float4* B4 = reinterpret_cast<const float4*>(B);
        for (int c = 0; c < OUT_F; c += 512) {
            for (int idx = t; idx < 512 * 4; idx += 256) {
                float4 v = B4[c * 4 + idx];
                s[idx * 4 + 0] = v.x;
                s[idx * 4 + 1] = v.y;
                s[idx * 4 + 2] = v.z;
                s[idx * 4 + 3] = v.w;
            }
            __syncthreads();
            for (int j = 0; j < 512; ++j)
                sum += s[j * 16 + r1] * s[j * 16 + r2];
            __syncthreads();
        }
        g_KB[t] = sum;
    }
}

// =====================================================================
// K2: Newton-Schulz on the 16x16 core (rank-16 algebraic reduction)
// =====================================================================
__global__ void k_ns() {
    __shared__ float KA[256], KB[256], C[256], T[256], D[256], E[256], F[256], G2[256];
    __shared__ float s_alpha;
    int t = threadIdx.x;
    int i = t >> 4, j = t & 15;
    KA[t] = g_KA[t];
    KB[t] = g_KB[t];
    __syncthreads();
    if (t == 0) {
        float n2 = 0.f;
        for (int p = 0; p < 16; ++p)
            for (int q = 0; q < 16; ++q)
                n2 += KB[p * 16 + q] * KA[q * 16 + p];
        s_alpha = sqrtf(n2);
    }
    __syncthreads();
    float alpha = s_alpha;
    float sc = 1.f / (alpha + NS_EPS);
    C[t] = (i == j) ? sc : 0.f;
    __syncthreads();

    for (int it = 0; it < 5; ++it) {
        float acc = 0.f;
        #pragma unroll
        for (int k = 0; k < 16; ++k) acc += KB[i * 16 + k] * C[k * 16 + j];
        T[t] = acc; __syncthreads();

        acc = 0.f;
        #pragma unroll
        for (int k = 0; k < 16; ++k) acc += C[k * 16 + i] * T[k * 16 + j];
        D[t] = acc; __syncthreads();

        acc = 0.f;
        #pragma unroll
        for (int k = 0; k < 16; ++k) acc += KA[i * 16 + k] * D[k * 16 + j];
        E[t] = acc; __syncthreads();

        acc = 0.f;
        #pragma unroll
        for (int k = 0; k < 16; ++k) acc += C[i * 16 + k] * E[k * 16 + j];
        F[t] = acc; __syncthreads();

        acc = 0.f;
        #pragma unroll
        for (int k = 0; k < 16; ++k) acc += F[i * 16 + k] * E[k * 16 + j];
        G2[t] = acc; __syncthreads();

        float cn = NS_A * C[t] + NS_Bc * F[t] + NS_Cc * G2[t];
        C[t] = cn;
        __syncthreads();
    }
    g_Cs[t] = alpha * C[t];
}

// =====================================================================
// K3: xA = bf16(x @ A^T)  [8192,32], cols 16..31 zeroed
// =====================================================================
__global__ void k_xa(const float* __restrict__ x, const float* __restrict__ A) {
    int w = threadIdx.x >> 5, l = threadIdx.x & 31;
    int i0 = (blockIdx.x * 8 + w) * 4;
    const float4* x4 = reinterpret_cast<const float4*>(x);
    const float4* A4 = reinterpret_cast<const float4*>(A);
    const int KQ = IN_F / 4;

    float acc[4][16];
    #pragma unroll
    for (int rr = 0; rr < 4; ++rr)
        #pragma unroll
        for (int r = 0; r < 16; ++r) acc[rr][r] = 0.f;

    for (int tt = 0; tt < 32; ++tt) {
        int k4 = l + (tt << 5);
        float4 xv0 = x4[(i0 + 0) * KQ + k4];
        float4 xv1 = x4[(i0 + 1) * KQ + k4];
        float4 xv2 = x4[(i0 + 2) * KQ + k4];
        float4 xv3 = x4[(i0 + 3) * KQ + k4];
        #pragma unroll
        for (int r = 0; r < 16; ++r) {
            float4 av = A4[r * KQ + k4];
            acc[0][r] += xv0.x * av.x + xv0.y * av.y + xv0.z * av.z + xv0.w * av.w;
            acc[1][r] += xv1.x * av.x + xv1.y * av.y + xv1.z * av.z + xv1.w * av.w;
            acc[2][r] += xv2.x * av.x + xv2.y * av.y + xv2.z * av.z + xv2.w * av.w;
            acc[3][r] += xv3.x * av.x + xv3.y * av.y + xv3.z * av.z + xv3.w * av.w;
        }
    }
    #pragma unroll
    for (int rr = 0; rr < 4; ++rr)
        #pragma unroll
        for (int r = 0; r < 16; ++r)
            #pragma unroll
            for (int off = 16; off; off >>= 1)
                acc[rr][r] += __shfl_xor_sync(0xffffffffu, acc[rr][r], off);
    __nv_bfloat16 z = __float2bfloat16(0.f);
    #pragma unroll
    for (int rr = 0; rr < 4; ++rr) {
        #pragma unroll
        for (int r = 0; r < 16; ++r)
            if (l == r) g_xAh[(i0 + rr) * 32 + r] = __float2bfloat16_rn(acc[rr][r]);
        if (l >= 16) g_xAh[(i0 + rr) * 32 + l] = z;   // zero cols 16..31
    }
}

// =====================================================================
// K4: Bc = bf16(B @ (alpha*C5))  [4096,32] padded
// =====================================================================
__global__ void k_bc(const float* __restrict__ B) {
    __shared__ float Cs[256];
    int t = threadIdx.x;
    Cs[t] = g_Cs[t];
    __syncthreads();
    int g = blockIdx.x * 256 + t;
    int j = g >> 4, r2 = g & 15;
    float s = 0.f;
    #pragma unroll
    for (int r = 0; r < 16; ++r) s += B[j * 16 + r] * Cs[r * 16 + r2];
    g_Bch[j * 32 + r2] = __float2bfloat16_rn(s);
    g_Bch[j * 32 + r2 + 16] = __float2bfloat16(0.f);
}

// =====================================================================
// K5: fused mma.sync bf16 GEMM.  CTA 128x128, BK=32, 4-stage cp.async.
//   Virtual K phases: xhi*whi | xhi*wlo | xlo*whi | lora(xA,Bc).
// =====================================================================
__device__ __forceinline__ void chunk_src(int i, const __nv_bfloat16*& xp,
                                          const __nv_bfloat16*& wp,
                                          int& pitch, int& k0) {
    if (i < 128)       { xp = g_xhi; wp = g_whi; pitch = IN_F; k0 = i << 5; }
    else if (i < 256)  { xp = g_xhi; wp = g_wlo; pitch = IN_F; k0 = (i - 128) << 5; }
    else if (i < 384)  { xp = g_xlo; wp = g_whi; pitch = IN_F; k0 = (i - 256) << 5; }
    else               { xp = g_xAh; wp = g_Bch; pitch = 32;   k0 = 0; }
}

__device__ __forceinline__ void issue_loads(int i, int t, int row0, int col0,
                                            uint32_t sA, uint32_t sB) {
    const __nv_bfloat16 *xp, *wp;
    int pitch, k0;
    chunk_src(i, xp, wp, pitch, k0);
    int r = t >> 1;              // 0..127
    uint32_t cb0 = (t & 1) * 2;  // {0, 2}
    const __nv_bfloat16* ga = xp + (size_t)(row0 + r) * pitch + k0 + cb0 * 8;
    cp16(sA + sw(r, cb0),     ga);
    cp16(sA + sw(r, cb0 + 1), ga + 8);
    const __nv_bfloat16* gb = wp + (size_t)(col0 + r) * pitch + k0 + cb0 * 8;
    cp16(sB + sw(r, cb0),     gb);
    cp16(sB + sw(r, cb0 + 1), gb + 8);
}

__global__ void __launch_bounds__(256, 2)
k_main(const float* __restrict__ bias, float* __restrict__ out) {
    extern __shared__ __align__(16) char dsm[];
    uint32_t sbase = smem_u32(dsm);

    int t = threadIdx.x;
    int wid = t >> 5, lane = t & 31;
    int warp_m = wid & 3, warp_n = wid >> 2;
    int m_base = warp_m * 32, n_base = warp_n * 64;
    int row0 = blockIdx.y << 7, col0 = blockIdx.x << 7;

    // per-thread ldmatrix row/col-phase decomposition
    int sel = lane >> 3, r8 = lane & 7;
    int aRow0 = m_base + (sel & 1) * 8 + r8;      // + mt*16
    int aCbH  = sel >> 1;                         // + ks*2
    int bRow0 = n_base + (sel >> 1) * 8 + r8;     // + g*16
    int bCbH  = sel & 1;                          // + ks*2

    float acc[2][8][4];
    #pragma unroll
    for (int mt = 0; mt < 2; ++mt)
        #pragma unroll
        for (int nt = 0; nt < 8; ++nt)
            #pragma unroll
            for (int q = 0; q < 4; ++q) acc[mt][nt][q] = 0.f;

    // prologue: fill 4 stages
    #pragma unroll
    for (int s = 0; s < STAGES; ++s) {
        issue_loads(s, t, row0, col0,
                    sbase + s * STAGE_BYTES, sbase + s * STAGE_BYTES + 8192);
        cp_commit();
    }

    for (int i = 0; i < NCH; ++i) {
        if (i + 3 < NCH)      cp_wait<3>();
        else if (i + 2 < NCH) cp_wait<2>();
        else if (i + 1 < NCH) cp_wait<1>();
        else                  cp_wait<0>();
        __syncthreads();

        uint32_t stA = sbase + (i & 3) * STAGE_BYTES;
        uint32_t stB = stA + 8192;

        #pragma unroll
        for (int ks = 0; ks < 2; ++ks) {
            uint32_t af[2][4], bf[4][4];
            #pragma unroll
            for (int mt = 0; mt < 2; ++mt)
                ldsm4(af[mt], stA + sw(aRow0 + mt * 16, ks * 2 + aCbH));
            #pragma unroll
            for (int g = 0; g < 4; ++g)
                ldsm4(bf[g], stB + sw(bRow0 + g * 16, ks * 2 + bCbH));
            #pragma unroll
            for (int mt = 0; mt < 2; ++mt)
                #pragma unroll
                for (int nt = 0; nt < 8; ++nt) {
                    int g = nt >> 1, h = (nt & 1) * 2;
                    mma16816(acc[mt][nt], af[mt], bf[g][h], bf[g][h + 1]);
                }
        }
        __syncthreads();

        if (i + STAGES < NCH) {
            issue_loads(i + STAGES, t, row0, col0, stA, stB);  // same stage slot
            cp_commit();
        }
    }

    // ---- epilogue: + bias, store fp32 ----
    int gid = lane >> 2, tid4 = lane & 3;
    float2 bv[8];
    #pragma unroll
    for (int nt = 0; nt < 8; ++nt)
        bv[nt] = *reinterpret_cast<const float2*>(bias + col0 + n_base + nt * 8 + tid4 * 2);

    #pragma unroll
    for (int mt = 0; mt < 2; ++mt) {
        int ra = row0 + m_base + mt * 16 + gid;
        int rb = ra + 8;
        #pragma unroll
        for (int nt = 0; nt < 8; ++nt) {
            int col = col0 + n_base + nt * 8 + tid4 * 2;
            float2 oa = make_float2(acc[mt][nt][0] + bv[nt].x, acc[mt][nt][1] + bv[nt].y);
            float2 ob = make_float2(acc[mt][nt][2] + bv[nt].x, acc[mt][nt][3] + bv[nt].y);
            *reinterpret_cast<float2*>(out + (size_t)ra * OUT_F + col) = oa;
            *reinterpret_cast<float2*>(out + (size_t)rb * OUT_F + col) = ob;
        }
    }
}

// =====================================================================
extern "C" void kernel_launch(void* const* d_in, const int* in_sizes, int n_in,
                              void* d_out, int out_size) {
    const float* x    = (const float*)d_in[0];   // [8192, 4096]
    const float* W    = (const float*)d_in[1];   // [4096, 4096]
    const float* bias = (const float*)d_in[2];   // [4096]
    const float* A    = (const float*)d_in[3];   // [16, 4096]
    const float* B    = (const float*)d_in[4];   // [4096, 16]
    float* out = (float*)d_out;                  // [8192, 4096]

    k_split_x<<<TOKENS * IN_F / 1024, 256>>>(reinterpret_cast<const float4*>(x));
    k_split_w<<<OUT_F * IN_F / 1024, 256>>>(reinterpret_cast<const float4*>(W));
    k_gram<<<2, 256>>>(A, B);
    k_ns<<<1, 256>>>();
    k_bc<<<256, 256>>>(B);
    k_xa<<<TOKENS / 32, 256>>>(x, A);

    const int SMEM_DYN = STAGES * STAGE_BYTES;   // 64 KB
    cudaFuncSetAttribute(k_main, cudaFuncAttributeMaxDynamicSharedMemorySize, SMEM_DYN);
    dim3 grid(OUT_F / 128, TOKENS / 128);
    k_main<<<grid, 256, SMEM_DYN>>>(bias, out);
}

// round 13
// speedup vs baseline: 2.5495x; 1.2211x over previous
#include <cuda_runtime.h>
#include <cuda_bf16.h>
#include <cstdint>

#define TOKENS 8192
#define IN_F   4096
#define OUT_F  4096
#define RNK    16

#define NS_A 3.4445f
#define NS_Bc (-4.775f)
#define NS_Cc 2.0315f
#define NS_EPS 1e-7f

#define NCH 193            // 3*64 split-bf16 chunks (BK=64) + 1 LoRA chunk
#define STAGES 4
#define A_STAGE 32768      // 256 rows x 128B
#define B_STAGE 16384      // 128 rows x 128B
#define STAGE_BYTES (A_STAGE + B_STAGE)   // 48KB

// ---------------- device scratch (no allocations allowed) ----------------
__device__ __align__(16) __nv_bfloat16 g_xhi[TOKENS * IN_F];
__device__ __align__(16) __nv_bfloat16 g_xlo[TOKENS * IN_F];
__device__ __align__(16) __nv_bfloat16 g_whi[OUT_F * IN_F];
__device__ __align__(16) __nv_bfloat16 g_wlo[OUT_F * IN_F];
__device__ __align__(16) __nv_bfloat16 g_xAh[TOKENS * 64];  // bf16(x@A^T), cols 16..63 zero
__device__ __align__(16) __nv_bfloat16 g_Bch[OUT_F * 64];   // bf16(B @ alpha*C5), padded
__device__ float g_KA[RNK * RNK];
__device__ float g_KB[RNK * RNK];
__device__ float g_Cs[RNK * RNK];

// ---------------- PTX helpers (sm_80-baseline instructions only) ----------
__device__ __forceinline__ uint32_t smem_u32(const void* p) {
    uint32_t a;
    asm("{ .reg .u64 t; cvta.to.shared.u64 t, %1; cvt.u32.u64 %0, t; }" : "=r"(a) : "l"(p));
    return a;
}
__device__ __forceinline__ void cp16(uint32_t s, const void* g) {
    asm volatile("cp.async.cg.shared.global [%0], [%1], 16;" :: "r"(s), "l"(g));
}
__device__ __forceinline__ void cp_commit() {
    asm volatile("cp.async.commit_group;" ::: "memory");
}
template <int N>
__device__ __forceinline__ void cp_wait() {
    asm volatile("cp.async.wait_group %0;" :: "n"(N) : "memory");
}
__device__ __forceinline__ void ldsm4(uint32_t* d, uint32_t a) {
    asm volatile("ldmatrix.sync.aligned.m8n8.x4.shared.b16 {%0,%1,%2,%3}, [%4];"
                 : "=r"(d[0]), "=r"(d[1]), "=r"(d[2]), "=r"(d[3]) : "r"(a));
}
__device__ __forceinline__ void mma16816(float* d, const uint32_t* a, uint32_t b0, uint32_t b1) {
    asm volatile(
        "mma.sync.aligned.m16n8k16.row.col.f32.bf16.bf16.f32 "
        "{%0,%1,%2,%3}, {%4,%5,%6,%7}, {%8,%9}, {%0,%1,%2,%3};"
        : "+f"(d[0]), "+f"(d[1]), "+f"(d[2]), "+f"(d[3])
        : "r"(a[0]), "r"(a[1]), "r"(a[2]), "r"(a[3]), "r"(b0), "r"(b1));
}

// swizzled smem byte offset for row-major [rows][64] bf16 tile (128B rows).
// cb in 16B units (0..7); conflict-free for 8-row ldmatrix groups.
__device__ __forceinline__ uint32_t sw(uint32_t row, uint32_t cb) {
    return row * 128u + ((cb ^ (row & 7u)) << 4);
}

// =====================================================================
// split fp32 -> bf16 hi + bf16 residual
// =====================================================================
__device__ __forceinline__ void split1(float v, unsigned short& h, unsigned short& l) {
    __nv_bfloat16 hb = __float2bfloat16_rn(v);
    h = __bfloat16_as_ushort(hb);
    float r = v - __bfloat162float(hb);
    l = __bfloat16_as_ushort(__float2bfloat16_rn(r));
}
__global__ void k_split_x(const float4* __restrict__ src) {
    int i = blockIdx.x * 256 + threadIdx.x;
    float4 v = src[i];
    ushort4 h, l;
    split1(v.x, h.x, l.x); split1(v.y, h.y, l.y);
    split1(v.z, h.z, l.z); split1(v.w, h.w, l.w);
    reinterpret_cast<ushort4*>(g_xhi)[i] = h;
    reinterpret_cast<ushort4*>(g_xlo)[i] = l;
}
__global__ void k_split_w(const float4* __restrict__ src) {
    int i = blockIdx.x * 256 + threadIdx.x;
    float4 v = src[i];
    ushort4 h, l;
    split1(v.x, h.x, l.x); split1(v.y, h.y, l.y);
    split1(v.z, h.z, l.z); split1(v.w, h.w, l.w);
    reinterpret_cast<ushort4*>(g_whi)[i] = h;
    reinterpret_cast<ushort4*>(g_wlo)[i] = l;
}

// =====================================================================
// K1: gram matrices. block 0: K_A = A A^T ; block 1: K_B = B^T B
// =====================================================================
__global__ void k_gram(const float* __restrict__ A, const float* __restrict__ B) {
    __shared__ float s[16 * 513];
    int t = threadIdx.x;
    int r1 = t >> 4, r2 = t & 15;
    float sum = 0.f;

    if (blockIdx.x == 0) {
        const float4* A4 = reinterpret_cast<const float4*>(A);
        for (int c = 0; c < IN_F; c += 512) {
            for (int idx = t; idx < 16 * 128; idx += 256) {
                int r = idx >> 7;
                int k4 = idx & 127;
                float4 v = A4[r * (IN_F / 4) + (c >> 2) + k4];
                s[r * 513 + k4 * 4 + 0] = v.x;
                s[r * 513 + k4 * 4 + 1] = v.y;
                s[r * 513 + k4 * 4 + 2] = v.z;
                s[r * 513 + k4 * 4 + 3] = v.w;
            }
            __syncthreads();
            for (int k = 0; k < 512; ++k)
                sum += s[r1 * 513 + k] * s[r2 * 513 + k];
            __syncthreads();
        }
        g_KA[t] = sum;
    } else {
        const float4* B4 = reinterpret_cast<const float4*>(B);
        for (int c = 0; c < OUT_F; c += 512) {
            for (int idx = t; idx < 512 * 4; idx += 256) {
                float4 v = B4[c * 4 + idx];
                s[idx * 4 + 0] = v.x;
                s[idx * 4 + 1] = v.y;
                s[idx * 4 + 2] = v.z;
                s[idx * 4 + 3] = v.w;
            }
            __syncthreads();
            for (int j = 0; j < 512; ++j)
                sum += s[j * 16 + r1] * s[j * 16 + r2];
            __syncthreads();
        }
        g_KB[t] = sum;
    }
}

// =====================================================================
// K2: Newton-Schulz on the 16x16 core (rank-16 algebraic reduction)
// =====================================================================
__global__ void k_ns() {
    __shared__ float KA[256], KB[256], C[256], T[256], D[256], E[256], F[256], G2[256];
    __shared__ float s_alpha;
    int t = threadIdx.x;
    int i = t >> 4, j = t & 15;
    KA[t] = g_KA[t];
    KB[t] = g_KB[t];
    __syncthreads();
    if (t == 0) {
        float n2 = 0.f;
        for (int p = 0; p < 16; ++p)
            for (int q = 0; q < 16; ++q)
                n2 += KB[p * 16 + q] * KA[q * 16 + p];
        s_alpha = sqrtf(n2);
    }
    __syncthreads();
    float alpha = s_alpha;
    float sc = 1.f / (alpha + NS_EPS);
    C[t] = (i == j) ? sc : 0.f;
    __syncthreads();

    for (int it = 0; it < 5; ++it) {
        float acc = 0.f;
        #pragma unroll
        for (int k = 0; k < 16; ++k) acc += KB[i * 16 + k] * C[k * 16 + j];
        T[t] = acc; __syncthreads();

        acc = 0.f;
        #pragma unroll
        for (int k = 0; k < 16; ++k) acc += C[k * 16 + i] * T[k * 16 + j];
        D[t] = acc; __syncthreads();

        acc = 0.f;
        #pragma unroll
        for (int k = 0; k < 16; ++k) acc += KA[i * 16 + k] * D[k * 16 + j];
        E[t] = acc; __syncthreads();

        acc = 0.f;
        #pragma unroll
        for (int k = 0; k < 16; ++k) acc += C[i * 16 + k] * E[k * 16 + j];
        F[t] = acc; __syncthreads();

        acc = 0.f;
        #pragma unroll
        for (int k = 0; k < 16; ++k) acc += F[i * 16 + k] * E[k * 16 + j];
        G2[t] = acc; __syncthreads();

        float cn = NS_A * C[t] + NS_Bc * F[t] + NS_Cc * G2[t];
        C[t] = cn;
        __syncthreads();
    }
    g_Cs[t] = alpha * C[t];
}

// =====================================================================
// K3: xA = bf16(x @ A^T)  [8192,64], cols 16..63 zeroed
// =====================================================================
__global__ void k_xa(const float* __restrict__ x, const float* __restrict__ A) {
    int w = threadIdx.x >> 5, l = threadIdx.x & 31;
    int i0 = (blockIdx.x * 8 + w) * 4;
    const float4* x4 = reinterpret_cast<const float4*>(x);
    const float4* A4 = reinterpret_cast<const float4*>(A);
    const int KQ = IN_F / 4;

    float acc[4][16];
    #pragma unroll
    for (int rr = 0; rr < 4; ++rr)
        #pragma unroll
        for (int r = 0; r < 16; ++r) acc[rr][r] = 0.f;

    for (int tt = 0; tt < 32; ++tt) {
        int k4 = l + (tt << 5);
        float4 xv0 = x4[(i0 + 0) * KQ + k4];
        float4 xv1 = x4[(i0 + 1) * KQ + k4];
        float4 xv2 = x4[(i0 + 2) * KQ + k4];
        float4 xv3 = x4[(i0 + 3) * KQ + k4];
        #pragma unroll
        for (int r = 0; r < 16; ++r) {
            float4 av = A4[r * KQ + k4];
            acc[0][r] += xv0.x * av.x + xv0.y * av.y + xv0.z * av.z + xv0.w * av.w;
            acc[1][r] += xv1.x * av.x + xv1.y * av.y + xv1.z * av.z + xv1.w * av.w;
            acc[2][r] += xv2.x * av.x + xv2.y * av.y + xv2.z * av.z + xv2.w * av.w;
            acc[3][r] += xv3.x * av.x + xv3.y * av.y + xv3.z * av.z + xv3.w * av.w;
        }
    }
    #pragma unroll
    for (int rr = 0; rr < 4; ++rr)
        #pragma unroll
        for (int r = 0; r < 16; ++r)
            #pragma unroll
            for (int off = 16; off; off >>= 1)
                acc[rr][r] += __shfl_xor_sync(0xffffffffu, acc[rr][r], off);
    __nv_bfloat16 z = __float2bfloat16(0.f);
    #pragma unroll
    for (int rr = 0; rr < 4; ++rr) {
        #pragma unroll
        for (int r = 0; r < 16; ++r)
            if (l == r) g_xAh[(i0 + rr) * 64 + r] = __float2bfloat16_rn(acc[rr][r]);
        if (l >= 16) {   // zero padding cols 16..63
            g_xAh[(i0 + rr) * 64 + l]      = z;
            g_xAh[(i0 + rr) * 64 + l + 16] = z;
            g_xAh[(i0 + rr) * 64 + l + 32] = z;
        }
    }
}

// =====================================================================
// K4: Bc = bf16(B @ (alpha*C5))  [4096,64] padded
// =====================================================================
__global__ void k_bc(const float* __restrict__ B) {
    __shared__ float Cs[256];
    int t = threadIdx.x;
    Cs[t] = g_Cs[t];
    __syncthreads();
    int g = blockIdx.x * 256 + t;
    int j = g >> 4, r2 = g & 15;
    float s = 0.f;
    #pragma unroll
    for (int r = 0; r < 16; ++r) s += B[j * 16 + r] * Cs[r * 16 + r2];
    __nv_bfloat16 z = __float2bfloat16(0.f);
    g_Bch[j * 64 + r2] = __float2bfloat16_rn(s);
    g_Bch[j * 64 + r2 + 16] = z;
    g_Bch[j * 64 + r2 + 32] = z;
    g_Bch[j * 64 + r2 + 48] = z;
}

// =====================================================================
// K5: fused mma.sync bf16 GEMM.  CTA 256x128, 8 warps of 64x64, BK=64,
//     4-stage cp.async (192KB), one __syncthreads per chunk.
//   Virtual K phases: xhi*whi | xhi*wlo | xlo*whi | lora(xA,Bc).
// =====================================================================
__device__ __forceinline__ void chunk_src(int i, const __nv_bfloat16*& xp,
                                          const __nv_bfloat16*& wp,
                                          int& pitch, int& k0) {
    if (i < 64)        { xp = g_xhi; wp = g_whi; pitch = IN_F; k0 = i << 6; }
    else if (i < 128)  { xp = g_xhi; wp = g_wlo; pitch = IN_F; k0 = (i - 64) << 6; }
    else if (i < 192)  { xp = g_xlo; wp = g_whi; pitch = IN_F; k0 = (i - 128) << 6; }
    else               { xp = g_xAh; wp = g_Bch; pitch = 64;   k0 = 0; }
}

__device__ __forceinline__ void issue_loads(int i, int t, int row0, int col0,
                                            uint32_t sA, uint32_t sB) {
    const __nv_bfloat16 *xp, *wp;
    int pitch, k0;
    chunk_src(i, xp, wp, pitch, k0);
    uint32_t cb = t & 7;
    int rbase = t >> 3;           // 0..31
    // A: 256 rows, 8 per thread
    #pragma unroll
    for (int k = 0; k < 8; ++k) {
        int r = rbase + k * 32;
        cp16(sA + sw(r, cb), xp + (size_t)(row0 + r) * pitch + k0 + cb * 8);
    }
    // B: 128 rows, 4 per thread
    #pragma unroll
    for (int k = 0; k < 4; ++k) {
        int r = rbase + k * 32;
        cp16(sB + sw(r, cb), wp + (size_t)(col0 + r) * pitch + k0 + cb * 8);
    }
}

__global__ void __launch_bounds__(256, 1)
k_main(const float* __restrict__ bias, float* __restrict__ out) {
    extern __shared__ __align__(16) char dsm[];
    uint32_t sbase = smem_u32(dsm);

    int t = threadIdx.x;
    int wid = t >> 5, lane = t & 31;
    int warp_m = wid & 3, warp_n = wid >> 2;
    int m_base = warp_m * 64, n_base = warp_n * 64;
    int row0 = blockIdx.y << 8, col0 = blockIdx.x << 7;

    // per-thread ldmatrix row/col-phase decomposition (same mapping as R10)
    int sel = lane >> 3, r8 = lane & 7;
    int aRow0 = m_base + (sel & 1) * 8 + r8;      // + mt*16
    int aCbH  = sel >> 1;                         // + ks*2
    int bRow0 = n_base + (sel >> 1) * 8 + r8;     // + g*16
    int bCbH  = sel & 1;                          // + ks*2

    float acc[4][8][4];
    #pragma unroll
    for (int mt = 0; mt < 4; ++mt)
        #pragma unroll
        for (int nt = 0; nt < 8; ++nt)
            #pragma unroll
            for (int q = 0; q < 4; ++q) acc[mt][nt][q] = 0.f;

    // prologue: fill STAGES-1 stages
    #pragma unroll
    for (int s = 0; s < STAGES - 1; ++s) {
        issue_loads(s, t, row0, col0,
                    sbase + s * STAGE_BYTES, sbase + s * STAGE_BYTES + A_STAGE);
        cp_commit();
    }

    for (int i = 0; i < NCH; ++i) {
        if (i + 3 < NCH)      cp_wait<2>();
        else if (i + 2 < NCH) cp_wait<1>();
        else                  cp_wait<0>();
        __syncthreads();

        // issue chunk i+STAGES-1 into the slot computed last iteration
        if (i + STAGES - 1 < NCH) {
            int s = (i + STAGES - 1) & 3;
            issue_loads(i + STAGES - 1, t, row0, col0,
                        sbase + s * STAGE_BYTES, sbase + s * STAGE_BYTES + A_STAGE);
            cp_commit();
        }

        uint32_t stA = sbase + (i & 3) * STAGE_BYTES;
        uint32_t stB = stA + A_STAGE;

        #pragma unroll
        for (int ks = 0; ks < 4; ++ks) {
            uint32_t af[4][4], bf[4][4];
            #pragma unroll
            for (int mt = 0; mt < 4; ++mt)
                ldsm4(af[mt], stA + sw(aRow0 + mt * 16, ks * 2 + aCbH));
            #pragma unroll
            for (int g = 0; g < 4; ++g)
                ldsm4(bf[g], stB + sw(bRow0 + g * 16, ks * 2 + bCbH));
            #pragma unroll
            for (int mt = 0; mt < 4; ++mt)
                #pragma unroll
                for (int nt = 0; nt < 8; ++nt) {
                    int g = nt >> 1, h = (nt & 1) * 2;
                    mma16816(acc[mt][nt], af[mt], bf[g][h], bf[g][h + 1]);
                }
        }
    }

    // ---- epilogue: + bias, store fp32 ----
    int gid = lane >> 2, tid4 = lane & 3;
    float2 bv[8];
    #pragma unroll
    for (int nt = 0; nt < 8; ++nt)
        bv[nt] = *reinterpret_cast<const float2*>(bias + col0 + n_base + nt * 8 + tid4 * 2);

    #pragma unroll
    for (int mt = 0; mt < 4; ++mt) {
        int ra = row0 + m_base + mt * 16 + gid;
        int rb = ra + 8;
        #pragma unroll
        for (int nt = 0; nt < 8; ++nt) {
            int col = col0 + n_base + nt * 8 + tid4 * 2;
            float2 oa = make_float2(acc[mt][nt][0] + bv[nt].x, acc[mt][nt][1] + bv[nt].y);
            float2 ob = make_float2(acc[mt][nt][2] + bv[nt].x, acc[mt][nt][3] + bv[nt].y);
            *reinterpret_cast<float2*>(out + (size_t)ra * OUT_F + col) = oa;
            *reinterpret_cast<float2*>(out + (size_t)rb * OUT_F + col) = ob;
        }
    }
}

// =====================================================================
extern "C" void kernel_launch(void* const* d_in, const int* in_sizes, int n_in,
                              void* d_out, int out_size) {
    const float* x    = (const float*)d_in[0];   // [8192, 4096]
    const float* W    = (const float*)d_in[1];   // [4096, 4096]
    const float* bias = (const float*)d_in[2];   // [4096]
    const float* A    = (const float*)d_in[3];   // [16, 4096]
    const float* B    = (const float*)d_in[4];   // [4096, 16]
    float* out = (float*)d_out;                  // [8192, 4096]

    k_split_x<<<TOKENS * IN_F / 1024, 256>>>(reinterpret_cast<const float4*>(x));
    k_split_w<<<OUT_F * IN_F / 1024, 256>>>(reinterpret_cast<const float4*>(W));
    k_gram<<<2, 256>>>(A, B);
    k_ns<<<1, 256>>>();
    k_bc<<<256, 256>>>(B);
    k_xa<<<TOKENS / 32, 256>>>(x, A);

    const int SMEM_DYN = STAGES * STAGE_BYTES;   // 192 KB
    cudaFuncSetAttribute(k_main, cudaFuncAttributeMaxDynamicSharedMemorySize, SMEM_DYN);
    dim3 grid(OUT_F / 128, TOKENS / 256);
    k_main<<<grid, 256, SMEM_DYN>>>(bias, out);
}

// round 15
// speedup vs baseline: 2.7876x; 1.0934x over previous
#include <cuda_runtime.h>
#include <cuda_bf16.h>
#include <cstdint>

#define TOKENS 8192
#define IN_F   4096
#define OUT_F  4096
#define RNK    16

#define NS_A 3.4445f
#define NS_Bc (-4.775f)
#define NS_Cc 2.0315f
#define NS_EPS 1e-7f

#define NCH 193            // 3*64 split-bf16 chunks (BK=64) + 1 LoRA chunk
#define STAGES 4
#define A_STAGE 32768      // 256 rows x 128B
#define B_STAGE 16384      // 128 rows x 128B
#define STAGE_BYTES (A_STAGE + B_STAGE)   // 48KB

// ---------------- device scratch (no allocations allowed) ----------------
__device__ __align__(16) __nv_bfloat16 g_xhi[TOKENS * IN_F];
__device__ __align__(16) __nv_bfloat16 g_xlo[TOKENS * IN_F];
__device__ __align__(16) __nv_bfloat16 g_whi[OUT_F * IN_F];
__device__ __align__(16) __nv_bfloat16 g_wlo[OUT_F * IN_F];
__device__ __align__(16) __nv_bfloat16 g_xAh[TOKENS * 64];  // bf16(x@A^T), cols 16..63 zero
__device__ __align__(16) __nv_bfloat16 g_Bch[OUT_F * 64];   // bf16(B @ alpha*C5), padded
__device__ float g_KA[RNK * RNK];
__device__ float g_KB[RNK * RNK];
__device__ float g_Cs[RNK * RNK];

// ---------------- PTX helpers (sm_80-baseline instructions only) ----------
__device__ __forceinline__ uint32_t smem_u32(const void* p) {
    uint32_t a;
    asm("{ .reg .u64 t; cvta.to.shared.u64 t, %1; cvt.u32.u64 %0, t; }" : "=r"(a) : "l"(p));
    return a;
}
__device__ __forceinline__ void cp16(uint32_t s, const void* g) {
    asm volatile("cp.async.cg.shared.global [%0], [%1], 16;" :: "r"(s), "l"(g));
}
__device__ __forceinline__ void cp_commit() {
    asm volatile("cp.async.commit_group;" ::: "memory");
}
template <int N>
__device__ __forceinline__ void cp_wait() {
    asm volatile("cp.async.wait_group %0;" :: "n"(N) : "memory");
}
__device__ __forceinline__ void ldsm4(uint32_t* d, uint32_t a) {
    asm volatile("ldmatrix.sync.aligned.m8n8.x4.shared.b16 {%0,%1,%2,%3}, [%4];"
                 : "=r"(d[0]), "=r"(d[1]), "=r"(d[2]), "=r"(d[3]) : "r"(a));
}
__device__ __forceinline__ void mma16816(float* d, const uint32_t* a, uint32_t b0, uint32_t b1) {
    asm volatile(
        "mma.sync.aligned.m16n8k16.row.col.f32.bf16.bf16.f32 "
        "{%0,%1,%2,%3}, {%4,%5,%6,%7}, {%8,%9}, {%0,%1,%2,%3};"
        : "+f"(d[0]), "+f"(d[1]), "+f"(d[2]), "+f"(d[3])
        : "r"(a[0]), "r"(a[1]), "r"(a[2]), "r"(a[3]), "r"(b0), "r"(b1));
}

// swizzled smem byte offset for row-major [rows][64] bf16 tile (128B rows).
// cb in 16B units (0..7); conflict-free for 8-row ldmatrix groups.
__device__ __forceinline__ uint32_t sw(uint32_t row, uint32_t cb) {
    return row * 128u + ((cb ^ (row & 7u)) << 4);
}

// =====================================================================
// split fp32 -> bf16 hi + bf16 residual
// =====================================================================
__device__ __forceinline__ void split1(float v, unsigned short& h, unsigned short& l) {
    __nv_bfloat16 hb = __float2bfloat16_rn(v);
    h = __bfloat16_as_ushort(hb);
    float r = v - __bfloat162float(hb);
    l = __bfloat16_as_ushort(__float2bfloat16_rn(r));
}
__global__ void k_split_x(const float4* __restrict__ src) {
    int i = blockIdx.x * 256 + threadIdx.x;
    float4 v = src[i];
    ushort4 h, l;
    split1(v.x, h.x, l.x); split1(v.y, h.y, l.y);
    split1(v.z, h.z, l.z); split1(v.w, h.w, l.w);
    reinterpret_cast<ushort4*>(g_xhi)[i] = h;
    reinterpret_cast<ushort4*>(g_xlo)[i] = l;
}
__global__ void k_split_w(const float4* __restrict__ src) {
    int i = blockIdx.x * 256 + threadIdx.x;
    float4 v = src[i];
    ushort4 h, l;
    split1(v.x, h.x, l.x); split1(v.y, h.y, l.y);
    split1(v.z, h.z, l.z); split1(v.w, h.w, l.w);
    reinterpret_cast<ushort4*>(g_whi)[i] = h;
    reinterpret_cast<ushort4*>(g_wlo)[i] = l;
}

// =====================================================================
// K1: gram matrices. block 0: K_A = A A^T ; block 1: K_B = B^T B
// =====================================================================
__global__ void k_gram(const float* __restrict__ A, const float* __restrict__ B) {
    __shared__ float s[16 * 513];
    int t = threadIdx.x;
    int r1 = t >> 4, r2 = t & 15;
    float sum = 0.f;

    if (blockIdx.x == 0) {
        const float4* A4 = reinterpret_cast<const float4*>(A);
        for (int c = 0; c < IN_F; c += 512) {
            for (int idx = t; idx < 16 * 128; idx += 256) {
                int r = idx >> 7;
                int k4 = idx & 127;
                float4 v = A4[r * (IN_F / 4) + (c >> 2) + k4];
                s[r * 513 + k4 * 4 + 0] = v.x;
                s[r * 513 + k4 * 4 + 1] = v.y;
                s[r * 513 + k4 * 4 + 2] = v.z;
                s[r * 513 + k4 * 4 + 3] = v.w;
            }
            __syncthreads();
            for (int k = 0; k < 512; ++k)
                sum += s[r1 * 513 + k] * s[r2 * 513 + k];
            __syncthreads();
        }
        g_KA[t] = sum;
    } else {
        const float4* B4 = reinterpret_cast<const float4*>(B);
        for (int c = 0; c < OUT_F; c += 512) {
            for (int idx = t; idx < 512 * 4; idx += 256) {
                float4 v = B4[c * 4 + idx];
                s[idx * 4 + 0] = v.x;
                s[idx * 4 + 1] = v.y;
                s[idx * 4 + 2] = v.z;
                s[idx * 4 + 3] = v.w;
            }
            __syncthreads();
            for (int j = 0; j < 512; ++j)
                sum += s[j * 16 + r1] * s[j * 16 + r2];
            __syncthreads();
        }
        g_KB[t] = sum;
    }
}

// =====================================================================
// K2: Newton-Schulz on the 16x16 core (rank-16 algebraic reduction)
// =====================================================================
__global__ void k_ns() {
    __shared__ float KA[256], KB[256], C[256], T[256], D[256], E[256], F[256], G2[256];
    __shared__ float s_alpha;
    int t = threadIdx.x;
    int i = t >> 4, j = t & 15;
    KA[t] = g_KA[t];
    KB[t] = g_KB[t];
    __syncthreads();
    if (t == 0) {
        float n2 = 0.f;
        for (int p = 0; p < 16; ++p)
            for (int q = 0; q < 16; ++q)
                n2 += KB[p * 16 + q] * KA[q * 16 + p];
        s_alpha = sqrtf(n2);
    }
    __syncthreads();
    float alpha = s_alpha;
    float sc = 1.f / (alpha + NS_EPS);
    C[t] = (i == j) ? sc : 0.f;
    __syncthreads();

    for (int it = 0; it < 5; ++it) {
        float acc = 0.f;
        #pragma unroll
        for (int k = 0; k < 16; ++k) acc += KB[i * 16 + k] * C[k * 16 + j];
        T[t] = acc; __syncthreads();

        acc = 0.f;
        #pragma unroll
        for (int k = 0; k < 16; ++k) acc += C[k * 16 + i] * T[k * 16 + j];
        D[t] = acc; __syncthreads();

        acc = 0.f;
        #pragma unroll
        for (int k = 0; k < 16; ++k) acc += KA[i * 16 + k] * D[k * 16 + j];
        E[t] = acc; __syncthreads();

        acc = 0.f;
        #pragma unroll
        for (int k = 0; k < 16; ++k) acc += C[i * 16 + k] * E[k * 16 + j];
        F[t] = acc; __syncthreads();

        acc = 0.f;
        #pragma unroll
        for (int k = 0; k < 16; ++k) acc += F[i * 16 + k] * E[k * 16 + j];
        G2[t] = acc; __syncthreads();

        float cn = NS_A * C[t] + NS_Bc * F[t] + NS_Cc * G2[t];
        C[t] = cn;
        __syncthreads();
    }
    g_Cs[t] = alpha * C[t];
}

// =====================================================================
// K3: xA = bf16(x @ A^T)  [8192,64], cols 16..63 zeroed
// =====================================================================
__global__ void k_xa(const float* __restrict__ x, const float* __restrict__ A) {
    int w = threadIdx.x >> 5, l = threadIdx.x & 31;
    int i0 = (blockIdx.x * 8 + w) * 4;
    const float4* x4 = reinterpret_cast<const float4*>(x);
    const float4* A4 = reinterpret_cast<const float4*>(A);
    const int KQ = IN_F / 4;

    float acc[4][16];
    #pragma unroll
    for (int rr = 0; rr < 4; ++rr)
        #pragma unroll
        for (int r = 0; r < 16; ++r) acc[rr][r] = 0.f;

    for (int tt = 0; tt < 32; ++tt) {
        int k4 = l + (tt << 5);
        float4 xv0 = x4[(i0 + 0) * KQ + k4];
        float4 xv1 = x4[(i0 + 1) * KQ + k4];
        float4 xv2 = x4[(i0 + 2) * KQ + k4];
        float4 xv3 = x4[(i0 + 3) * KQ + k4];
        #pragma unroll
        for (int r = 0; r < 16; ++r) {
            float4 av = A4[r * KQ + k4];
            acc[0][r] += xv0.x * av.x + xv0.y * av.y + xv0.z * av.z + xv0.w * av.w;
            acc[1][r] += xv1.x * av.x + xv1.y * av.y + xv1.z * av.z + xv1.w * av.w;
            acc[2][r] += xv2.x * av.x + xv2.y * av.y + xv2.z * av.z + xv2.w * av.w;
            acc[3][r] += xv3.x * av.x + xv3.y * av.y + xv3.z * av.z + xv3.w * av.w;
        }
    }
    #pragma unroll
    for (int rr = 0; rr < 4; ++rr)
        #pragma unroll
        for (int r = 0; r < 16; ++r)
            #pragma unroll
            for (int off = 16; off; off >>= 1)
                acc[rr][r] += __shfl_xor_sync(0xffffffffu, acc[rr][r], off);
    __nv_bfloat16 z = __float2bfloat16(0.f);
    #pragma unroll
    for (int rr = 0; rr < 4; ++rr) {
        #pragma unroll
        for (int r = 0; r < 16; ++r)
            if (l == r) g_xAh[(i0 + rr) * 64 + r] = __float2bfloat16_rn(acc[rr][r]);
        if (l >= 16) {   // zero padding cols 16..63
            g_xAh[(i0 + rr) * 64 + l]      = z;
            g_xAh[(i0 + rr) * 64 + l + 16] = z;
            g_xAh[(i0 + rr) * 64 + l + 32] = z;
        }
    }
}

// =====================================================================
// K4: Bc = bf16(B @ (alpha*C5))  [4096,64] padded
// =====================================================================
__global__ void k_bc(const float* __restrict__ B) {
    __shared__ float Cs[256];
    int t = threadIdx.x;
    Cs[t] = g_Cs[t];
    __syncthreads();
    int g = blockIdx.x * 256 + t;
    int j = g >> 4, r2 = g & 15;
    float s = 0.f;
    #pragma unroll
    for (int r = 0; r < 16; ++r) s += B[j * 16 + r] * Cs[r * 16 + r2];
    __nv_bfloat16 z = __float2bfloat16(0.f);
    g_Bch[j * 64 + r2] = __float2bfloat16_rn(s);
    g_Bch[j * 64 + r2 + 16] = z;
    g_Bch[j * 64 + r2 + 32] = z;
    g_Bch[j * 64 + r2 + 48] = z;
}

// =====================================================================
// K5: fused mma.sync bf16 GEMM.  CTA 256x128, 8 warps of 64x64, BK=64,
//     4-stage cp.async (192KB), register-fragment double buffering
//     across ks AND across the chunk boundary.
//   Virtual K phases: xhi*whi | xhi*wlo | xlo*whi | lora(xA,Bc).
// =====================================================================
__device__ __forceinline__ void chunk_src(int i, const __nv_bfloat16*& xp,
                                          const __nv_bfloat16*& wp,
                                          int& pitch, int& k0) {
    if (i < 64)        { xp = g_xhi; wp = g_whi; pitch = IN_F; k0 = i << 6; }
    else if (i < 128)  { xp = g_xhi; wp = g_wlo; pitch = IN_F; k0 = (i - 64) << 6; }
    else if (i < 192)  { xp = g_xlo; wp = g_whi; pitch = IN_F; k0 = (i - 128) << 6; }
    else               { xp = g_xAh; wp = g_Bch; pitch = 64;   k0 = 0; }
}

__device__ __forceinline__ void issue_loads(int i, int t, int row0, int col0,
                                            uint32_t sA, uint32_t sB) {
    const __nv_bfloat16 *xp, *wp;
    int pitch, k0;
    chunk_src(i, xp, wp, pitch, k0);
    uint32_t cb = t & 7;
    int rbase = t >> 3;           // 0..31
    #pragma unroll
    for (int k = 0; k < 8; ++k) {
        int r = rbase + k * 32;
        cp16(sA + sw(r, cb), xp + (size_t)(row0 + r) * pitch + k0 + cb * 8);
    }
    #pragma unroll
    for (int k = 0; k < 4; ++k) {
        int r = rbase + k * 32;
        cp16(sB + sw(r, cb), wp + (size_t)(col0 + r) * pitch + k0 + cb * 8);
    }
}

__global__ void __launch_bounds__(256, 1)
k_main(const float* __restrict__ bias, float* __restrict__ out) {
    extern __shared__ __align__(16) char dsm[];
    uint32_t sbase = smem_u32(dsm);

    int t = threadIdx.x;
    int wid = t >> 5, lane = t & 31;
    int warp_m = wid & 3, warp_n = wid >> 2;
    int m_base = warp_m * 64, n_base = warp_n * 64;
    int row0 = blockIdx.y << 8, col0 = blockIdx.x << 7;

    // per-thread ldmatrix row/col-phase decomposition
    int sel = lane >> 3, r8 = lane & 7;
    int aRow0 = m_base + (sel & 1) * 8 + r8;      // + mt*16
    int aCbH  = sel >> 1;                         // + ks*2
    int bRow0 = n_base + (sel >> 1) * 8 + r8;     // + g*16
    int bCbH  = sel & 1;                          // + ks*2

    float acc[4][8][4];
    #pragma unroll
    for (int mt = 0; mt < 4; ++mt)
        #pragma unroll
        for (int nt = 0; nt < 8; ++nt)
            #pragma unroll
            for (int q = 0; q < 4; ++q) acc[mt][nt][q] = 0.f;

    // prologue: fill STAGES-1 stages (chunks 0,1,2)
    #pragma unroll
    for (int s = 0; s < STAGES - 1; ++s) {
        issue_loads(s, t, row0, col0,
                    sbase + s * STAGE_BYTES, sbase + s * STAGE_BYTES + A_STAGE);
        cp_commit();
    }
    cp_wait<1>();           // chunks 0 and 1 resident
    __syncthreads();

    // fragment double buffers; preload (chunk 0, ks 0)
    uint32_t af[2][4][4], bf[2][4][4];
    {
        uint32_t stA = sbase, stB = sbase + A_STAGE;
        #pragma unroll
        for (int mt = 0; mt < 4; ++mt) ldsm4(af[0][mt], stA + sw(aRow0 + mt * 16, aCbH));
        #pragma unroll
        for (int g = 0; g < 4; ++g)    ldsm4(bf[0][g],  stB + sw(bRow0 + g * 16, bCbH));
    }

    for (int i = 0; i < NCH; ++i) {
        // issue chunk i+3 into stage (i+3)&3 (stage (i-1)&3: drained last iter)
        if (i + STAGES - 1 < NCH) {
            int s = (i + STAGES - 1) & 3;
            issue_loads(i + STAGES - 1, t, row0, col0,
                        sbase + s * STAGE_BYTES, sbase + s * STAGE_BYTES + A_STAGE);
            cp_commit();
        }

        uint32_t stA = sbase + (i & 3) * STAGE_BYTES;
        uint32_t stB = stA + A_STAGE;
        uint32_t stAn = sbase + ((i + 1) & 3) * STAGE_BYTES;
        uint32_t stBn = stAn + A_STAGE;

        #pragma unroll
        for (int ks = 0; ks < 4; ++ks) {
            int cur = ks & 1, nxt = cur ^ 1;
            // prefetch next fragments (same chunk ks+1, or chunk i+1 ks0)
            if (ks < 3) {
                #pragma unroll
                for (int mt = 0; mt < 4; ++mt)
                    ldsm4(af[nxt][mt], stA + sw(aRow0 + mt * 16, (ks + 1) * 2 + aCbH));
                #pragma unroll
                for (int g = 0; g < 4; ++g)
                    ldsm4(bf[nxt][g], stB + sw(bRow0 + g * 16, (ks + 1) * 2 + bCbH));
            } else if (i + 1 < NCH) {
                #pragma unroll
                for (int mt = 0; mt < 4; ++mt)
                    ldsm4(af[nxt][mt], stAn + sw(aRow0 + mt * 16, aCbH));
                #pragma unroll
                for (int g = 0; g < 4; ++g)
                    ldsm4(bf[nxt][g], stBn + sw(bRow0 + g * 16, bCbH));
            }
            #pragma unroll
            for (int mt = 0; mt < 4; ++mt)
                #pragma unroll
                for (int nt = 0; nt < 8; ++nt) {
                    int g = nt >> 1, h = (nt & 1) * 2;
                    mma16816(acc[mt][nt], af[cur][mt], bf[cur][g][h], bf[cur][g][h + 1]);
                }
        }

        // make chunk i+2 resident for next iteration's tail prefetch;
        // sync so next iteration may overwrite stage (i+4)&3 = i&3
        if (i + 1 < NCH) {
            if (i + STAGES - 1 < NCH) cp_wait<1>();
            else                      cp_wait<0>();
            __syncthreads();
        }
    }

    // ---- epilogue: + bias, store fp32 ----
    int gid = lane >> 2, tid4 = lane & 3;
    float2 bv[8];
    #pragma unroll
    for (int nt = 0; nt < 8; ++nt)
        bv[nt] = *reinterpret_cast<const float2*>(bias + col0 + n_base + nt * 8 + tid4 * 2);

    #pragma unroll
    for (int mt = 0; mt < 4; ++mt) {
        int ra = row0 + m_base + mt * 16 + gid;
        int rb = ra + 8;
        #pragma unroll
        for (int nt = 0; nt < 8; ++nt) {
            int col = col0 + n_base + nt * 8 + tid4 * 2;
            float2 oa = make_float2(acc[mt][nt][0] + bv[nt].x, acc[mt][nt][1] + bv[nt].y);
            float2 ob = make_float2(acc[mt][nt][2] + bv[nt].x, acc[mt][nt][3] + bv[nt].y);
            *reinterpret_cast<float2*>(out + (size_t)ra * OUT_F + col) = oa;
            *reinterpret_cast<float2*>(out + (size_t)rb * OUT_F + col) = ob;
        }
    }
}

// =====================================================================
extern "C" void kernel_launch(void* const* d_in, const int* in_sizes, int n_in,
                              void* d_out, int out_size) {
    const float* x    = (const float*)d_in[0];   // [8192, 4096]
    const float* W    = (const float*)d_in[1];   // [4096, 4096]
    const float* bias = (const float*)d_in[2];   // [4096]
    const float* A    = (const float*)d_in[3];   // [16, 4096]
    const float* B    = (const float*)d_in[4];   // [4096, 16]
    float* out = (float*)d_out;                  // [8192, 4096]

    k_split_x<<<TOKENS * IN_F / 1024, 256>>>(reinterpret_cast<const float4*>(x));
    k_split_w<<<OUT_F * IN_F / 1024, 256>>>(reinterpret_cast<const float4*>(W));
    k_gram<<<2, 256>>>(A, B);
    k_ns<<<1, 256>>>();
    k_bc<<<256, 256>>>(B);
    k_xa<<<TOKENS / 32, 256>>>(x, A);

    const int SMEM_DYN = STAGES * STAGE_BYTES;   // 192 KB
    cudaFuncSetAttribute(k_main, cudaFuncAttributeMaxDynamicSharedMemorySize, SMEM_DYN);
    dim3 grid(OUT_F / 128, TOKENS / 256);
    k_main<<<grid, 256, SMEM_DYN>>>(bias, out);
}